// round 15
// baseline (speedup 1.0000x reference)
#include <cuda_runtime.h>
#include <cuda_fp16.h>
#include <cstdint>

// ---------------- problem dims (fixed) ----------------
#define B_DIM   1024
#define IN_DIM  4096
#define OUT_DIM 4096
#define NB      1024          // IN_DIM / 4 quant blocks per row
#define NX_BLOCKS (B_DIM * NB)      // 1,048,576  (x quant blocks)

// ---------------- GEMM tiling (R7 skeleton, R13 protocol) ----------------
#define BM 128
#define BN 256
#define BK 64                  // fine chunk: 128 bytes per smem row
#define BIG 128                // coarse stage = 2 fine chunks
#define NITER (IN_DIM / BIG)   // 32
#define A_BYTES (BM * 128)                    // 16 KB per fine chunk
#define B_BYTES (BN * 128)                    // 32 KB per fine chunk
#define CHUNK_BYTES (A_BYTES + B_BYTES)       // 48 KB
#define STAGE_BYTES (2 * CHUNK_BYTES)         // 96 KB coarse stage
#define SMEM_TOTAL (2 * STAGE_BYTES)          // 192 KB, 2 coarse stages
#define NCOL 16                // grid.x
#define NGEMM 128              // GEMM CTAs (= producers of 32-row W slices)

// ---------------- scratch + counters (device globals: allocation-free) ----------------
__device__ __half g_Xh[(size_t)B_DIM * IN_DIM];    // 8 MB
__device__ __half g_Wh[(size_t)OUT_DIM * IN_DIM];  // 32 MB
__device__ int    g_wcnt[NITER];                   // arrivals per BIG chunk (full at 128)

// ---------------- helpers ----------------
__device__ __forceinline__ uint32_t smem_u32(const void* p) {
    uint32_t a;
    asm("{ .reg .u64 t; cvta.to.shared.u64 t, %1; cvt.u32.u64 %0, t; }" : "=r"(a) : "l"(p));
    return a;
}

__device__ __forceinline__ void cp_async16(uint32_t dst, const void* src) {
    asm volatile("cp.async.cg.shared.global [%0], [%1], 16;" :: "r"(dst), "l"(src) : "memory");
}
#define CP_COMMIT() asm volatile("cp.async.commit_group;" ::: "memory")
#define CP_WAIT(n)  asm volatile("cp.async.wait_group %0;" :: "n"(n) : "memory")

__device__ __forceinline__ void ldmatrix_x4(uint32_t& r0, uint32_t& r1, uint32_t& r2, uint32_t& r3,
                                            uint32_t addr) {
    asm volatile("ldmatrix.sync.aligned.m8n8.x4.shared.b16 {%0,%1,%2,%3}, [%4];"
                 : "=r"(r0), "=r"(r1), "=r"(r2), "=r"(r3) : "r"(addr));
}

__device__ __forceinline__ void mma16816(float* d, const uint32_t* a, const uint32_t* b) {
    asm volatile(
        "mma.sync.aligned.m16n8k16.row.col.f32.f16.f16.f32 "
        "{%0,%1,%2,%3}, {%4,%5,%6,%7}, {%8,%9}, {%0,%1,%2,%3};"
        : "+f"(d[0]), "+f"(d[1]), "+f"(d[2]), "+f"(d[3])
        : "r"(a[0]), "r"(a[1]), "r"(a[2]), "r"(a[3]), "r"(b[0]), "r"(b[1]));
}

// swizzled smem byte offset for (row, 16B-chunk)
__device__ __forceinline__ uint32_t swz(int row, int ch) {
    return (uint32_t)(row * 128 + ((ch ^ (row & 7)) << 4));
}

// ---------------- dequant math ----------------
__device__ __forceinline__ float fq(float v, float s, float z) {       // exact (x pre-pass)
    float q = rintf(v / s + z);
    q = fminf(fmaxf(q, 0.0f), 255.0f);
    return (q - z) * s;
}
__device__ __forceinline__ float fq_rs(float v, float s, float z, float rs) { // Newton-rcp path
    float q = rintf(fmaf(v, rs, z));
    q = fminf(fmaxf(q, 0.0f), 255.0f);
    return (q - z) * s;
}

union HalfPack { __half2 h2[2]; uint2 u; };

// ---------------- x dequant pre-pass (also zeroes the W chunk counters) ----------------
#define DQ_THREADS 256
#define DQ_PER_THREAD 8
#define DQ_PER_CTA (DQ_THREADS * DQ_PER_THREAD)   // 2048

__global__ void __launch_bounds__(DQ_THREADS, 4)
dequant_x_kernel(const float* __restrict__ x,  const float* __restrict__ xs,
                 const float* __restrict__ xz) {
    if (blockIdx.x == 0 && threadIdx.x < NITER)
        g_wcnt[threadIdx.x] = 0;

    int j0 = blockIdx.x * DQ_PER_CTA + threadIdx.x;
    float4 v[DQ_PER_THREAD];
    float  s[DQ_PER_THREAD], z[DQ_PER_THREAD];
#pragma unroll
    for (int u = 0; u < DQ_PER_THREAD; u++) {
        int j = j0 + u * DQ_THREADS;
        v[u] = reinterpret_cast<const float4*>(x)[j];
        int blk = j & (NB - 1);
        s[u] = __ldg(xs + blk);
        z[u] = __ldg(xz + blk);
    }
#pragma unroll
    for (int u = 0; u < DQ_PER_THREAD; u++) {
        HalfPack p;
        p.h2[0] = __floats2half2_rn(fq(v[u].x, s[u], z[u]), fq(v[u].y, s[u], z[u]));
        p.h2[1] = __floats2half2_rn(fq(v[u].z, s[u], z[u]), fq(v[u].w, s[u], z[u]));
        reinterpret_cast<uint2*>(g_Xh)[j0 + u * DQ_THREADS] = p.u;
    }
}

// ---------------- distributed W production: CTA r owns rows [32r, 32r+32) ----------------
struct WProd { float4 v[4]; float s[4], z[4]; };

__device__ __forceinline__ void wprod_issue(WProd& P, const float* __restrict__ w,
                                            const float* __restrict__ ws,
                                            const float* __restrict__ wz, int r, int p) {
    int lane = threadIdx.x & 31;
    int rw = threadIdx.x >> 5;            // 0..7
    int kc = p * BIG;
#pragma unroll
    for (int k = 0; k < 4; k++) {
        int grow = r * 32 + rw + k * 8;
        P.v[k] = __ldg(reinterpret_cast<const float4*>(w + (size_t)grow * IN_DIM + kc) + lane);
        int sidx = grow * NB + (kc >> 2) + lane;
        P.s[k] = __ldg(ws + sidx);
        P.z[k] = __ldg(wz + sidx);
    }
}

__device__ __forceinline__ void wprod_store(const WProd& P, int r, int p) {
    int lane = threadIdx.x & 31;
    int rw = threadIdx.x >> 5;
    int kc = p * BIG;
#pragma unroll
    for (int k = 0; k < 4; k++) {
        int grow = r * 32 + rw + k * 8;
        float s = P.s[k], z = P.z[k];
        float rs;
        asm("rcp.approx.f32 %0, %1;" : "=f"(rs) : "f"(s));
        rs = rs * (2.0f - s * rs);        // Newton: ~exact 1/s (verified R11/R13)
        HalfPack pk;
        pk.h2[0] = __floats2half2_rn(fq_rs(P.v[k].x, s, z, rs), fq_rs(P.v[k].y, s, z, rs));
        pk.h2[1] = __floats2half2_rn(fq_rs(P.v[k].z, s, z, rs), fq_rs(P.v[k].w, s, z, rs));
        *(reinterpret_cast<uint2*>(g_Wh + (size_t)grow * IN_DIM + kc) + lane) = pk.u;
    }
}

// relaxed peek: NO ordering constraint — MMA loads schedule around it freely
__device__ __forceinline__ int peek_relaxed(int p) {
    int c;
    asm volatile("ld.relaxed.gpu.global.s32 %0, [%1];" : "=r"(c) : "l"(&g_wcnt[p]));
    return c;
}
// acquire spin (fallback path only)
__device__ __forceinline__ void wait_chunk_acq(int p) {
    const int* f = &g_wcnt[p];
    int c;
    do {
        asm volatile("ld.acquire.gpu.global.s32 %0, [%1];" : "=r"(c) : "l"(f));
    } while (c < NGEMM);
}

// ---------------- fine-chunk loader: gmem(fp16) -> smem, 16B cp.async, swizzled ----------------
__device__ __forceinline__ void load_chunk(uint32_t sA, uint32_t sB, int m0, int n0, int kc) {
    int t = threadIdx.x;
#pragma unroll
    for (int i = 0; i < 4; i++) {                  // A: 128 rows x 8 chunks = 1024
        int idx = t + i * 256;
        int row = idx >> 3, ch = idx & 7;
        const __half* src = g_Xh + (size_t)(m0 + row) * IN_DIM + kc + ch * 8;
        cp_async16(sA + swz(row, ch), src);
    }
#pragma unroll
    for (int i = 0; i < 8; i++) {                  // B: 256 rows x 8 chunks = 2048
        int idx = t + i * 256;
        int row = idx >> 3, ch = idx & 7;
        const __half* src = g_Wh + (size_t)(n0 + row) * IN_DIM + kc + ch * 8;
        cp_async16(sB + swz(row, ch), src);
    }
}

__device__ __forceinline__ void load_stage(uint32_t slot, int m0, int n0, int kc) {
    load_chunk(slot, slot + A_BYTES, m0, n0, kc);
    load_chunk(slot + CHUNK_BYTES, slot + CHUNK_BYTES + A_BYTES, m0, n0, kc + BK);
}

// ---------------- GEMM: 128x256 tile/CTA + distributed in-flight W production ----------------
__global__ void __launch_bounds__(256, 1)
gemm_f16_kernel(const float* __restrict__ w,   const float* __restrict__ ws,
                const float* __restrict__ wz,
                const float* __restrict__ bias, float* __restrict__ out) {
    extern __shared__ char smem[];
    uint32_t sbase = smem_u32(smem);
    int tid = threadIdx.x;
    int wid = tid >> 5, lane = tid & 31;
    int bx = blockIdx.x, by = blockIdx.y;
    int m0 = by * BM;
    int n0 = bx * BN;
    int r  = by * NCOL + bx;      // 0..127: W-row-slice ownership
    int wm = (wid & 1) * 64;      // 2 (m) x 4 (n) warps, warp tile 64 x 64
    int wn = (wid >> 1) * 64;

    int lrow = lane & 15;         // ldmatrix x4: lanes 0-15 rows, 16-31 chunk+1
    int lch  = lane >> 4;

    float acc[4][8][4];
#pragma unroll
    for (int i = 0; i < 4; i++)
#pragma unroll
        for (int j = 0; j < 8; j++)
#pragma unroll
            for (int k = 0; k < 4; k++) acc[i][j][k] = 0.0f;

    // ---- prologue: produce my slices of chunks 0..2, publish, then load stage 0 ----
#pragma unroll 1
    for (int p = 0; p < 3; p++) {
        WProd P;
        wprod_issue(P, w, ws, wz, r, p);
        wprod_store(P, r, p);
    }
    __threadfence();              // my STGs device-visible
    __syncthreads();              // all threads fenced
    if (tid == 0) {
#pragma unroll
        for (int p = 0; p < 3; p++) atomicAdd(&g_wcnt[p], 1);
    }
    wait_chunk_acq(0);
    load_stage(sbase, m0, n0, 0);
    CP_COMMIT();

#pragma unroll 1
    for (int c = 0; c < NITER; ++c) {
        CP_WAIT(0);               // my copies for stage c retired
        __syncthreads();          // barA: stage c visible; orders last iter's W STGs

        // publish chunk c+2 (STGs happened last iteration, before barA)
        if (tid == 0 && c >= 1 && c + 2 < NITER) {
            __threadfence();
            atomicAdd(&g_wcnt[c + 2], 1);
        }

        // hoisted RELAXED peek of next chunk counter (in flight during MMA chunk 0)
        bool has_next = (c + 1) < NITER;
        int cnext = NGEMM;
        if (has_next) cnext = peek_relaxed(c + 1);

        // issue production LDGs for chunk c+3 (latency covered by MMA sub=0)
        WProd P;
        bool prod = (c + 3) < NITER;
        if (prod) wprod_issue(P, w, ws, wz, r, c + 3);

        uint32_t slot = sbase + (c & 1) * STAGE_BYTES;

        // ---- MMA fine chunk 0 of stage c ----
        {
            uint32_t sA = slot;
            uint32_t sB = sA + A_BYTES;
#pragma unroll
            for (int ks = 0; ks < 4; ks++) {
                uint32_t a[4][4];
#pragma unroll
                for (int i = 0; i < 4; i++) {
                    int row = wm + i * 16 + lrow;
                    ldmatrix_x4(a[i][0], a[i][1], a[i][2], a[i][3],
                                sA + swz(row, ks * 2 + lch));
                }
                uint32_t b[8][2];
#pragma unroll
                for (int j = 0; j < 4; j++) {
                    int row = wn + j * 16 + lrow;
                    uint32_t r0, r1, r2, r3;
                    ldmatrix_x4(r0, r1, r2, r3, sB + swz(row, ks * 2 + lch));
                    b[2 * j][0] = r0;     b[2 * j][1] = r2;
                    b[2 * j + 1][0] = r1; b[2 * j + 1][1] = r3;
                }
#pragma unroll
                for (int i = 0; i < 4; i++)
#pragma unroll
                    for (int j = 0; j < 8; j++)
                        mma16816(acc[i][j], a[i], b[j]);
            }
        }

        // ---- mid-iteration: peek already returned; spin only if it saw not-full ----
        if (has_next) {
            if (cnext < NGEMM) {
                wait_chunk_acq(c + 1);              // slow path: acquire spin
            } else {
                asm volatile("membar.gl;" ::: "memory");  // acquire fence; load done
            }
            load_stage(sbase + ((c + 1) & 1) * STAGE_BYTES, m0, n0, (c + 1) * BIG);
            CP_COMMIT();
        }

        // ---- production compute+store for chunk c+3 (LDGs have had ~3000 cyc) ----
        if (prod) wprod_store(P, r, c + 3);

        // ---- MMA fine chunk 1 of stage c ----
        {
            uint32_t sA = slot + CHUNK_BYTES;
            uint32_t sB = sA + A_BYTES;
#pragma unroll
            for (int ks = 0; ks < 4; ks++) {
                uint32_t a[4][4];
#pragma unroll
                for (int i = 0; i < 4; i++) {
                    int row = wm + i * 16 + lrow;
                    ldmatrix_x4(a[i][0], a[i][1], a[i][2], a[i][3],
                                sA + swz(row, ks * 2 + lch));
                }
                uint32_t b[8][2];
#pragma unroll
                for (int j = 0; j < 4; j++) {
                    int row = wn + j * 16 + lrow;
                    uint32_t r0, r1, r2, r3;
                    ldmatrix_x4(r0, r1, r2, r3, sB + swz(row, ks * 2 + lch));
                    b[2 * j][0] = r0;     b[2 * j][1] = r2;
                    b[2 * j + 1][0] = r1; b[2 * j + 1][1] = r3;
                }
#pragma unroll
                for (int i = 0; i < 4; i++)
#pragma unroll
                    for (int j = 0; j < 8; j++)
                        mma16816(acc[i][j], a[i], b[j]);
            }
        }
    }

    // epilogue: C frag -> gmem with bias. lane: g = lane/4 (row), c2 = (lane%4)*2 (col)
    int g = lane >> 2, c2 = (lane & 3) * 2;
#pragma unroll
    for (int i = 0; i < 4; i++) {
        int row = m0 + wm + i * 16 + g;
        float* r0p = out + (size_t)row * OUT_DIM;
        float* r1p = out + (size_t)(row + 8) * OUT_DIM;
#pragma unroll
        for (int j = 0; j < 8; j++) {
            int col = n0 + wn + j * 8 + c2;
            float b0 = __ldg(&bias[col]), b1 = __ldg(&bias[col + 1]);
            float2 v0 = make_float2(acc[i][j][0] + b0, acc[i][j][1] + b1);
            float2 v1 = make_float2(acc[i][j][2] + b0, acc[i][j][3] + b1);
            *reinterpret_cast<float2*>(r0p + col) = v0;
            *reinterpret_cast<float2*>(r1p + col) = v1;
        }
    }
}

// ---------------- launch ----------------
extern "C" void kernel_launch(void* const* d_in, const int* in_sizes, int n_in,
                              void* d_out, int out_size) {
    const float* x    = (const float*)d_in[0];
    const float* w    = (const float*)d_in[1];
    const float* bias = (const float*)d_in[2];
    const float* ws   = (const float*)d_in[3];
    const float* wz   = (const float*)d_in[4];
    const float* as_  = (const float*)d_in[5];
    const float* az   = (const float*)d_in[6];
    float* out = (float*)d_out;

    dequant_x_kernel<<<NX_BLOCKS / DQ_PER_CTA, DQ_THREADS>>>(x, as_, az);

    cudaFuncSetAttribute(gemm_f16_kernel, cudaFuncAttributeMaxDynamicSharedMemorySize, SMEM_TOTAL);
    dim3 grid(NCOL, 8);   // 128 CTAs, all resident simultaneously (required by protocol)
    gemm_f16_kernel<<<grid, 256, SMEM_TOTAL>>>(w, ws, wz, bias, out);
}

// round 16
// speedup vs baseline: 1.2688x; 1.2688x over previous
#include <cuda_runtime.h>
#include <cuda_fp16.h>
#include <cstdint>

// ---------------- problem dims (fixed) ----------------
#define B_DIM   1024
#define IN_DIM  4096
#define OUT_DIM 4096
#define NB      1024          // IN_DIM / 4 quant blocks per row

// ---------------- GEMM tiling (R7 skeleton, R13 protocol) ----------------
#define BM 128
#define BN 256
#define BK 64                  // fine chunk: 128 bytes per smem row
#define BIG 128                // coarse stage = 2 fine chunks
#define NITER (IN_DIM / BIG)   // 32
#define A_BYTES (BM * 128)                    // 16 KB per fine chunk
#define B_BYTES (BN * 128)                    // 32 KB per fine chunk
#define CHUNK_BYTES (A_BYTES + B_BYTES)       // 48 KB
#define STAGE_BYTES (2 * CHUNK_BYTES)         // 96 KB coarse stage
#define SMEM_TOTAL (2 * STAGE_BYTES)          // 192 KB, 2 coarse stages
#define NCOL 16                // grid.x
#define NGEMM 128              // CTAs: each produces 32 W rows + 8 X rows per chunk

// ---------------- scratch + counters (device globals: zero-init at load) ----------------
__device__ __half g_Xh[(size_t)B_DIM * IN_DIM];    // 8 MB
__device__ __half g_Wh[(size_t)OUT_DIM * IN_DIM];  // 32 MB
__device__ int    g_wcnt[NITER];                   // arrivals per BIG chunk (full at 128)
__device__ int    g_done;                          // CTA completion counter (reset protocol)

// ---------------- helpers ----------------
__device__ __forceinline__ uint32_t smem_u32(const void* p) {
    uint32_t a;
    asm("{ .reg .u64 t; cvta.to.shared.u64 t, %1; cvt.u32.u64 %0, t; }" : "=r"(a) : "l"(p));
    return a;
}

__device__ __forceinline__ void cp_async16(uint32_t dst, const void* src) {
    asm volatile("cp.async.cg.shared.global [%0], [%1], 16;" :: "r"(dst), "l"(src) : "memory");
}
#define CP_COMMIT() asm volatile("cp.async.commit_group;" ::: "memory")
#define CP_WAIT(n)  asm volatile("cp.async.wait_group %0;" :: "n"(n) : "memory")

__device__ __forceinline__ void ldmatrix_x4(uint32_t& r0, uint32_t& r1, uint32_t& r2, uint32_t& r3,
                                            uint32_t addr) {
    asm volatile("ldmatrix.sync.aligned.m8n8.x4.shared.b16 {%0,%1,%2,%3}, [%4];"
                 : "=r"(r0), "=r"(r1), "=r"(r2), "=r"(r3) : "r"(addr));
}

__device__ __forceinline__ void mma16816(float* d, const uint32_t* a, const uint32_t* b) {
    asm volatile(
        "mma.sync.aligned.m16n8k16.row.col.f32.f16.f16.f32 "
        "{%0,%1,%2,%3}, {%4,%5,%6,%7}, {%8,%9}, {%0,%1,%2,%3};"
        : "+f"(d[0]), "+f"(d[1]), "+f"(d[2]), "+f"(d[3])
        : "r"(a[0]), "r"(a[1]), "r"(a[2]), "r"(a[3]), "r"(b[0]), "r"(b[1]));
}

// swizzled smem byte offset for (row, 16B-chunk)
__device__ __forceinline__ uint32_t swz(int row, int ch) {
    return (uint32_t)(row * 128 + ((ch ^ (row & 7)) << 4));
}

// ---------------- dequant math (Newton-rcp path, verified R11/R13/R14) ----------------
__device__ __forceinline__ float fq_rs(float v, float s, float z, float rs) {
    float q = rintf(fmaf(v, rs, z));
    q = fminf(fmaxf(q, 0.0f), 255.0f);
    return (q - z) * s;
}
__device__ __forceinline__ float newton_rcp(float s) {
    float rs;
    asm("rcp.approx.f32 %0, %1;" : "=f"(rs) : "f"(s));
    return rs * (2.0f - s * rs);
}

union HalfPack { __half2 h2[2]; uint2 u; };

// ---------------- distributed production: CTA r owns W rows [32r,32r+32), X rows [8r,8r+8) ----------------
struct Prod {
    float4 wv[4]; float ws_[4], wz_[4];
    float4 xv;    float xs_,    xz_;
};

__device__ __forceinline__ void prod_issue(Prod& P,
        const float* __restrict__ w,  const float* __restrict__ ws, const float* __restrict__ wz,
        const float* __restrict__ x,  const float* __restrict__ xs, const float* __restrict__ xz,
        int r, int p) {
    int lane = threadIdx.x & 31;
    int rw = threadIdx.x >> 5;            // 0..7
    int kc = p * BIG;
#pragma unroll
    for (int k = 0; k < 4; k++) {
        int grow = r * 32 + rw + k * 8;
        P.wv[k] = __ldg(reinterpret_cast<const float4*>(w + (size_t)grow * IN_DIM + kc) + lane);
        int sidx = grow * NB + (kc >> 2) + lane;
        P.ws_[k] = __ldg(ws + sidx);
        P.wz_[k] = __ldg(wz + sidx);
    }
    {   // X: 8 rows x 32 float4; thread t -> row t>>5, block t&31
        int xrow = r * 8 + rw;
        P.xv = __ldg(reinterpret_cast<const float4*>(x + (size_t)xrow * IN_DIM + kc) + lane);
        int sidx = (kc >> 2) + lane;      // a_scales: per block, shared across rows
        P.xs_ = __ldg(xs + sidx);
        P.xz_ = __ldg(xz + sidx);
    }
}

__device__ __forceinline__ void prod_store(const Prod& P, int r, int p) {
    int lane = threadIdx.x & 31;
    int rw = threadIdx.x >> 5;
    int kc = p * BIG;
#pragma unroll
    for (int k = 0; k < 4; k++) {
        int grow = r * 32 + rw + k * 8;
        float s = P.ws_[k], z = P.wz_[k];
        float rs = newton_rcp(s);
        HalfPack pk;
        pk.h2[0] = __floats2half2_rn(fq_rs(P.wv[k].x, s, z, rs), fq_rs(P.wv[k].y, s, z, rs));
        pk.h2[1] = __floats2half2_rn(fq_rs(P.wv[k].z, s, z, rs), fq_rs(P.wv[k].w, s, z, rs));
        *(reinterpret_cast<uint2*>(g_Wh + (size_t)grow * IN_DIM + kc) + lane) = pk.u;
    }
    {
        int xrow = r * 8 + rw;
        float s = P.xs_, z = P.xz_;
        float rs = newton_rcp(s);
        HalfPack pk;
        pk.h2[0] = __floats2half2_rn(fq_rs(P.xv.x, s, z, rs), fq_rs(P.xv.y, s, z, rs));
        pk.h2[1] = __floats2half2_rn(fq_rs(P.xv.z, s, z, rs), fq_rs(P.xv.w, s, z, rs));
        *(reinterpret_cast<uint2*>(g_Xh + (size_t)xrow * IN_DIM + kc) + lane) = pk.u;
    }
}

// R13's proven wait: all-thread acquire spin, mid-iteration only
__device__ __forceinline__ void wait_chunk(int p) {
    const int* f = &g_wcnt[p];
    int c;
    do {
        asm volatile("ld.acquire.gpu.global.s32 %0, [%1];" : "=r"(c) : "l"(f));
    } while (c < NGEMM);
}

// ---------------- fine-chunk loader: gmem(fp16) -> smem, 16B cp.async, swizzled ----------------
__device__ __forceinline__ void load_chunk(uint32_t sA, uint32_t sB, int m0, int n0, int kc) {
    int t = threadIdx.x;
#pragma unroll
    for (int i = 0; i < 4; i++) {                  // A: 128 rows x 8 chunks = 1024
        int idx = t + i * 256;
        int row = idx >> 3, ch = idx & 7;
        const __half* src = g_Xh + (size_t)(m0 + row) * IN_DIM + kc + ch * 8;
        cp_async16(sA + swz(row, ch), src);
    }
#pragma unroll
    for (int i = 0; i < 8; i++) {                  // B: 256 rows x 8 chunks = 2048
        int idx = t + i * 256;
        int row = idx >> 3, ch = idx & 7;
        const __half* src = g_Wh + (size_t)(n0 + row) * IN_DIM + kc + ch * 8;
        cp_async16(sB + swz(row, ch), src);
    }
}

__device__ __forceinline__ void load_stage(uint32_t slot, int m0, int n0, int kc) {
    load_chunk(slot, slot + A_BYTES, m0, n0, kc);
    load_chunk(slot + CHUNK_BYTES, slot + CHUNK_BYTES + A_BYTES, m0, n0, kc + BK);
}

// ---------------- single fused kernel: GEMM + distributed X/W dequant (R13 protocol) ----------------
__global__ void __launch_bounds__(256, 1)
gemm_f16_kernel(const float* __restrict__ x,   const float* __restrict__ xs,
                const float* __restrict__ xz,
                const float* __restrict__ w,   const float* __restrict__ ws,
                const float* __restrict__ wz,
                const float* __restrict__ bias, float* __restrict__ out) {
    extern __shared__ char smem[];
    uint32_t sbase = smem_u32(smem);
    int tid = threadIdx.x;
    int wid = tid >> 5, lane = tid & 31;
    int bx = blockIdx.x, by = blockIdx.y;
    int m0 = by * BM;
    int n0 = bx * BN;
    int r  = by * NCOL + bx;      // 0..127: production ownership
    int wm = (wid & 1) * 64;      // 2 (m) x 4 (n) warps, warp tile 64 x 64
    int wn = (wid >> 1) * 64;

    int lrow = lane & 15;         // ldmatrix x4: lanes 0-15 rows, 16-31 chunk+1
    int lch  = lane >> 4;

    float acc[4][8][4];
#pragma unroll
    for (int i = 0; i < 4; i++)
#pragma unroll
        for (int j = 0; j < 8; j++)
#pragma unroll
            for (int k = 0; k < 4; k++) acc[i][j][k] = 0.0f;

    // ---- prologue: produce my X+W slices of chunks 0..2, publish, load stage 0 ----
#pragma unroll 1
    for (int p = 0; p < 3; p++) {
        Prod P;
        prod_issue(P, w, ws, wz, x, xs, xz, r, p);
        prod_store(P, r, p);
    }
    __threadfence();              // my STGs device-visible
    __syncthreads();              // all threads fenced
    if (tid == 0) {
#pragma unroll
        for (int p = 0; p < 3; p++) atomicAdd(&g_wcnt[p], 1);
    }
    wait_chunk(0);
    load_stage(sbase, m0, n0, 0);
    CP_COMMIT();

#pragma unroll 1
    for (int c = 0; c < NITER; ++c) {
        CP_WAIT(0);               // my copies for stage c retired
        __syncthreads();          // barA: stage c visible; orders last iter's prod STGs

        // publish chunk c+2 (STGs happened last iteration, before barA)
        if (tid == 0 && c >= 1 && c + 2 < NITER) {
            __threadfence();
            atomicAdd(&g_wcnt[c + 2], 1);
        }

        // issue production LDGs for chunk c+3 (latency covered by MMA sub=0)
        Prod P;
        bool prod = (c + 3) < NITER;
        if (prod) prod_issue(P, w, ws, wz, x, xs, xz, r, c + 3);

        uint32_t slot = sbase + (c & 1) * STAGE_BYTES;

        // ---- MMA fine chunk 0 of stage c ----
        {
            uint32_t sA = slot;
            uint32_t sB = sA + A_BYTES;
#pragma unroll
            for (int ks = 0; ks < 4; ks++) {
                uint32_t a[4][4];
#pragma unroll
                for (int i = 0; i < 4; i++) {
                    int row = wm + i * 16 + lrow;
                    ldmatrix_x4(a[i][0], a[i][1], a[i][2], a[i][3],
                                sA + swz(row, ks * 2 + lch));
                }
                uint32_t b[8][2];
#pragma unroll
                for (int j = 0; j < 4; j++) {
                    int row = wn + j * 16 + lrow;
                    uint32_t r0, r1, r2, r3;
                    ldmatrix_x4(r0, r1, r2, r3, sB + swz(row, ks * 2 + lch));
                    b[2 * j][0] = r0;     b[2 * j][1] = r2;
                    b[2 * j + 1][0] = r1; b[2 * j + 1][1] = r3;
                }
#pragma unroll
                for (int i = 0; i < 4; i++)
#pragma unroll
                    for (int j = 0; j < 8; j++)
                        mma16816(acc[i][j], a[i], b[j]);
            }
        }

        // ---- mid-iteration: wait next chunk (published >=1 iter ago), prefetch it ----
        if (c + 1 < NITER) {
            wait_chunk(c + 1);
            load_stage(sbase + ((c + 1) & 1) * STAGE_BYTES, m0, n0, (c + 1) * BIG);
            CP_COMMIT();
        }

        // ---- production compute+store for chunk c+3 (LDGs have had ~3000 cyc) ----
        if (prod) prod_store(P, r, c + 3);

        // ---- MMA fine chunk 1 of stage c ----
        {
            uint32_t sA = slot + CHUNK_BYTES;
            uint32_t sB = sA + A_BYTES;
#pragma unroll
            for (int ks = 0; ks < 4; ks++) {
                uint32_t a[4][4];
#pragma unroll
                for (int i = 0; i < 4; i++) {
                    int row = wm + i * 16 + lrow;
                    ldmatrix_x4(a[i][0], a[i][1], a[i][2], a[i][3],
                                sA + swz(row, ks * 2 + lch));
                }
                uint32_t b[8][2];
#pragma unroll
                for (int j = 0; j < 4; j++) {
                    int row = wn + j * 16 + lrow;
                    uint32_t r0, r1, r2, r3;
                    ldmatrix_x4(r0, r1, r2, r3, sB + swz(row, ks * 2 + lch));
                    b[2 * j][0] = r0;     b[2 * j][1] = r2;
                    b[2 * j + 1][0] = r1; b[2 * j + 1][1] = r3;
                }
#pragma unroll
                for (int i = 0; i < 4; i++)
#pragma unroll
                    for (int j = 0; j < 8; j++)
                        mma16816(acc[i][j], a[i], b[j]);
            }
        }
    }

    // epilogue: C frag -> gmem with bias. lane: g = lane/4 (row), c2 = (lane%4)*2 (col)
    int g = lane >> 2, c2 = (lane & 3) * 2;
#pragma unroll
    for (int i = 0; i < 4; i++) {
        int row = m0 + wm + i * 16 + g;
        float* r0p = out + (size_t)row * OUT_DIM;
        float* r1p = out + (size_t)(row + 8) * OUT_DIM;
#pragma unroll
        for (int j = 0; j < 8; j++) {
            int col = n0 + wn + j * 8 + c2;
            float b0 = __ldg(&bias[col]), b1 = __ldg(&bias[col + 1]);
            float2 v0 = make_float2(acc[i][j][0] + b0, acc[i][j][1] + b1);
            float2 v1 = make_float2(acc[i][j][2] + b0, acc[i][j][3] + b1);
            *reinterpret_cast<float2*>(r0p + col) = v0;
            *reinterpret_cast<float2*>(r1p + col) = v1;
        }
    }

    // ---- counter reset: last CTA out zeroes everything for the next graph replay.
    // Safe: g_done reaches NGEMM only after every CTA has passed all waits.
    if (tid == 0) {
        int d = atomicAdd(&g_done, 1);
        if (d == NGEMM - 1) {
#pragma unroll
            for (int p = 0; p < NITER; p++) atomicExch(&g_wcnt[p], 0);
            atomicExch(&g_done, 0);
        }
    }
}

// ---------------- launch: ONE kernel ----------------
extern "C" void kernel_launch(void* const* d_in, const int* in_sizes, int n_in,
                              void* d_out, int out_size) {
    const float* x    = (const float*)d_in[0];
    const float* w    = (const float*)d_in[1];
    const float* bias = (const float*)d_in[2];
    const float* ws   = (const float*)d_in[3];
    const float* wz   = (const float*)d_in[4];
    const float* as_  = (const float*)d_in[5];
    const float* az   = (const float*)d_in[6];
    float* out = (float*)d_out;

    cudaFuncSetAttribute(gemm_f16_kernel, cudaFuncAttributeMaxDynamicSharedMemorySize, SMEM_TOTAL);
    dim3 grid(NCOL, 8);   // 128 CTAs, all resident simultaneously (required by protocol)
    gemm_f16_kernel<<<grid, 256, SMEM_TOTAL>>>(x, as_, az, w, ws, wz, bias, out);
}